// round 6
// baseline (speedup 1.0000x reference)
#include <cuda_runtime.h>
#include <cstddef>

#define NSPEC 10
#define KCH   64
#define D     9
#define NA1   3
#define NA2   8
#define NA3   18
#define ATOT  29
#define NEK   (NSPEC * KCH)   // 640 (species, channel) combos
#define NM    220             // C(12,3): monomials i<=j<=l over 10 vars (v9 == 1)
#define ROWF  12              // padded floats per monomial row (9 outputs + 3 pad)
#define RROW  13              // reduction row stride (odd -> conflict-free banks)
#define Q1    55
#define Q2    110
#define Q3    165

// Scratch (device global — allocation-free per harness rules)
__device__ float g_S[(size_t)NEK * NM * ROWF];    // S[ek][m][o] symmetrized coeffs

// ---------------------------------------------------------------------------
// packed f32x2 helpers (sm_103a FFMA2 — PTX only)
// ---------------------------------------------------------------------------
__device__ __forceinline__ void ffma2(unsigned long long& d,
                                      unsigned long long a,
                                      unsigned long long b) {
    asm("fma.rn.f32x2 %0, %1, %2, %0;" : "+l"(d) : "l"(a), "l"(b));
}
__device__ __forceinline__ unsigned long long dup_f32(float t) {
    unsigned long long r;
    asm("mov.b64 %0, {%1, %1};" : "=l"(r) : "r"(__float_as_uint(t)));
    return r;
}
__device__ __forceinline__ void unpack2(unsigned long long p, float& lo, float& hi) {
    unsigned a, b;
    asm("mov.b64 {%0, %1}, %2;" : "=r"(a), "=r"(b) : "l"(p));
    lo = __uint_as_float(a); hi = __uint_as_float(b);
}

// ---------------------------------------------------------------------------
// Kernel B: symmetrized coefficients, wp folded in via re-association.
// One block per monomial m (220 blocks), 640 threads = (e,k).
//   Phase 1: UsT[b][o]  (symmetrized U, transposed, padded)
//   Phase 2: V[a][o] = sum_b proj[a][aoff+b] * UsT[b][o]   ((e,k)-independent)
//   Phase 3: S[ek][m][o] = sum_a w[e,a,k] * V[a][o]
// ---------------------------------------------------------------------------
__global__ void __launch_bounds__(NEK)
coeff_kernel(const float* __restrict__ w,
             const float* __restrict__ proj,
             const float* __restrict__ U1,
             const float* __restrict__ U2,
             const float* __restrict__ U3) {
    const int m = blockIdx.x;
    int mi = 9, mj = 9, ml = 9;
    {
        int c = 0;
        for (int i = 0; i < 10; i++)
            for (int j = i; j < 10; j++)
                for (int l = j; l < 10; l++) {
                    if (c == m) { mi = i; mj = j; ml = l; }
                    c++;
                }
    }
    const int deg  = (ml < 9) ? 3 : (mj < 9) ? 2 : (mi < 9) ? 1 : 0;
    const int aoff = (deg == 3) ? (NA1 + NA2) : (deg == 2) ? NA1 : 0;
    const int acnt = (deg == 3) ? NA3 : (deg == 2) ? NA2 : (deg == 1) ? NA1 : 0;

    __shared__ __align__(16) float UsT[NA3 * 12];   // [b][o], padded
    __shared__ __align__(16) float V[ATOT * 12];    // [a][o], padded

    const int t = threadIdx.x;
    if (t < NA3 * 12) UsT[t] = 0.f;
    __syncthreads();

    if (t < 9 * NA3) {
        int o = t / NA3, a = t % NA3;
        float s = 0.f;
        if (deg == 3) {
            int P[6][3] = {{mi,mj,ml},{mi,ml,mj},{mj,mi,ml},
                           {mj,ml,mi},{ml,mi,mj},{ml,mj,mi}};
#pragma unroll
            for (int p = 0; p < 6; p++) {
                bool dup = false;
#pragma unroll
                for (int q = 0; q < 6; q++)
                    if (q < p && P[q][0] == P[p][0] && P[q][1] == P[p][1] &&
                        P[q][2] == P[p][2]) dup = true;
                if (!dup)
                    s += U3[((((size_t)o * 9 + P[p][0]) * 9 + P[p][1]) * 9 + P[p][2]) * NA3 + a];
            }
        } else if (deg == 2 && a < NA2) {
            s = U2[(((size_t)o * 9 + mi) * 9 + mj) * NA2 + a];
            if (mi != mj)
                s += U2[(((size_t)o * 9 + mj) * 9 + mi) * NA2 + a];
        } else if (deg == 1 && a < NA1) {
            s = U1[((size_t)o * 9 + mi) * NA1 + a];
        }
        UsT[a * 12 + o] = s;
    }
    __syncthreads();

    // Phase 2: V[a][o], 29*9 = 261 entries (plus zero padding lanes)
    if (t < ATOT * 12) {
        int a = t / 12, o = t % 12;
        float s = 0.f;
        if (o < 9) {
            for (int b = 0; b < acnt; b++)
                s = fmaf(proj[a * ATOT + aoff + b], UsT[b * 12 + o], s);
        }
        V[a * 12 + o] = s;
    }
    __syncthreads();

    // Phase 3: per (e,k) thread
    const int e = t >> 6, k = t & 63;

    unsigned long long a01 = 0, a23 = 0, a45 = 0, a67 = 0;
    float a8 = 0.f;
#pragma unroll
    for (int a = 0; a < ATOT; a++) {
        float wa = w[((size_t)e * ATOT + a) * KCH + k];
        const float* row = V + a * 12;
        ulonglong2 cA = *(const ulonglong2*)row;
        ulonglong2 cB = *(const ulonglong2*)(row + 4);
        float c8 = row[8];
        unsigned long long wv = dup_f32(wa);
        ffma2(a01, cA.x, wv);
        ffma2(a23, cA.y, wv);
        ffma2(a45, cB.x, wv);
        ffma2(a67, cB.y, wv);
        a8 = fmaf(c8, wa, a8);
    }

    float c9[9];
    unpack2(a01, c9[0], c9[1]);
    unpack2(a23, c9[2], c9[3]);
    unpack2(a45, c9[4], c9[5]);
    unpack2(a67, c9[6], c9[7]);
    c9[8] = a8;

    float* dst = g_S + ((size_t)t * NM + m) * ROWF;
    ((float4*)dst)[0] = make_float4(c9[0], c9[1], c9[2], c9[3]);
    ((float4*)dst)[1] = make_float4(c9[4], c9[5], c9[6], c9[7]);
    dst[8] = c9[8];
}

// ---------------------------------------------------------------------------
// Eval inner body: accumulate monomials m in [MS, ME) into r[9].
// Fully unrolled; range guard folds at compile time.
// ---------------------------------------------------------------------------
template <int MS, int ME>
__device__ __forceinline__ void eval_range(const float* __restrict__ Cs,
                                           const float v[10], float r[9]) {
    unsigned long long a01 = 0, a23 = 0, a45 = 0, a67 = 0;
    float a8 = 0.f;
    int m = 0;
#pragma unroll
    for (int i = 0; i < 10; i++) {
#pragma unroll
        for (int j = i; j < 10; j++) {
            float pij = v[i] * v[j];
#pragma unroll
            for (int l = j; l < 10; l++) {
                if (m >= MS && m < ME) {
                    float tm = pij * v[l];
                    const float* row = Cs + m * ROWF;
                    ulonglong2 cA = *(const ulonglong2*)row;        // o0..3
                    ulonglong2 cB = *(const ulonglong2*)(row + 4);  // o4..7
                    float c8 = row[8];
                    unsigned long long tt = dup_f32(tm);
                    ffma2(a01, cA.x, tt);
                    ffma2(a23, cA.y, tt);
                    ffma2(a45, cB.x, tt);
                    ffma2(a67, cB.y, tt);
                    a8 = fmaf(c8, tm, a8);
                }
                m++;
            }
        }
    }
    unpack2(a01, r[0], r[1]);
    unpack2(a23, r[2], r[3]);
    unpack2(a45, r[4], r[5]);
    unpack2(a67, r[6], r[7]);
    r[8] = a8;
}

// ---------------------------------------------------------------------------
// Kernel C: evaluate. One block per (k, e), 512 threads.
//   atom = tid & 127, quarter = tid >> 7 sums 55 monomials each.
//   Quarters 1..3 dump partials to smem; quarter 0 reduces + stores.
// ---------------------------------------------------------------------------
__global__ void __launch_bounds__(512)
eval_kernel(const float* __restrict__ x,
            const int* __restrict__ counts,
            float* __restrict__ out) {
    const int k = blockIdx.x;
    const int e = blockIdx.y;
    const int ek = e * KCH + k;

    __shared__ __align__(16) float Cs[NM * ROWF];
    __shared__ float Red[3 * 128 * RROW];
    {
        const float4* src = (const float4*)(g_S + (size_t)ek * NM * ROWF);
        float4* dst = (float4*)Cs;
        for (int t = threadIdx.x; t < NM * ROWF / 4; t += blockDim.x)
            dst[t] = src[t];
    }

    int start = 0, cnt = 0;
#pragma unroll
    for (int t = 0; t < NSPEC; t++) {
        int c = counts[t];
        if (t < e) start += c;
        if (t == e) cnt = c;
    }
    __syncthreads();

    const int tid  = threadIdx.x;
    const int atom = tid & 127;
    const int q    = tid >> 7;
    const bool valid = atom < cnt;
    const int n = start + (valid ? atom : 0);

    const float* xp = x + ((size_t)n * KCH + k) * D;
    float v[10];
#pragma unroll
    for (int t = 0; t < 9; t++) v[t] = xp[t];
    v[9] = 1.f;

    float r[9];
    if (q == 0)      eval_range<0,  Q1>(Cs, v, r);
    else if (q == 1) eval_range<Q1, Q2>(Cs, v, r);
    else if (q == 2) eval_range<Q2, Q3>(Cs, v, r);
    else             eval_range<Q3, NM>(Cs, v, r);

    if (q != 0) {
        float* rr = Red + ((q - 1) * 128 + atom) * RROW;
#pragma unroll
        for (int o = 0; o < 9; o++) rr[o] = r[o];
    }
    __syncthreads();

    if (q == 0 && valid) {
        const float* r1 = Red + (0 * 128 + atom) * RROW;
        const float* r2 = Red + (1 * 128 + atom) * RROW;
        const float* r3 = Red + (2 * 128 + atom) * RROW;
        float* op = out + ((size_t)n * KCH + k) * D;
#pragma unroll
        for (int o = 0; o < 9; o++)
            op[o] = (r[o] + r1[o]) + (r2[o] + r3[o]);
    }
}

// ---------------------------------------------------------------------------
extern "C" void kernel_launch(void* const* d_in, const int* in_sizes, int n_in,
                              void* d_out, int out_size) {
    const float* x      = (const float*)d_in[0];
    const int*   counts = (const int*)  d_in[1];
    const float* w      = (const float*)d_in[2];
    const float* proj   = (const float*)d_in[3];
    const float* U1     = (const float*)d_in[4];
    const float* U2     = (const float*)d_in[5];
    const float* U3     = (const float*)d_in[6];
    float* out = (float*)d_out;

    coeff_kernel<<<NM, NEK>>>(w, proj, U1, U2, U3);
    dim3 grid(KCH, NSPEC);
    eval_kernel<<<grid, 512>>>(x, counts, out);
}

// round 7
// speedup vs baseline: 1.2221x; 1.2221x over previous
#include <cuda_runtime.h>
#include <cstddef>

#define NSPEC 10
#define KCH   64
#define D     9
#define NA1   3
#define NA2   8
#define NA3   18
#define ATOT  29
#define NEK   (NSPEC * KCH)   // 640 (species, channel) combos
#define NM    220             // C(12,3): monomials i<=j<=l over 10 vars (v9 == 1)
#define ROWF  12              // padded floats per monomial row (9 outputs + 3 pad)
#define RROW  13              // reduction/x row stride (odd -> conflict-free banks)
#define Q1    55
#define Q2    110
#define Q3    165

// Scratch (device global — allocation-free per harness rules)
__device__ float g_S[(size_t)NEK * NM * ROWF];    // S[ek][m][o] symmetrized coeffs

// ---------------------------------------------------------------------------
// packed f32x2 helpers (sm_103a FFMA2 — PTX only)
// ---------------------------------------------------------------------------
__device__ __forceinline__ void ffma2(unsigned long long& d,
                                      unsigned long long a,
                                      unsigned long long b) {
    asm("fma.rn.f32x2 %0, %1, %2, %0;" : "+l"(d) : "l"(a), "l"(b));
}
__device__ __forceinline__ unsigned long long dup_f32(float t) {
    unsigned long long r;
    asm("mov.b64 %0, {%1, %1};" : "=l"(r) : "r"(__float_as_uint(t)));
    return r;
}
__device__ __forceinline__ void unpack2(unsigned long long p, float& lo, float& hi) {
    unsigned a, b;
    asm("mov.b64 {%0, %1}, %2;" : "=r"(a), "=r"(b) : "l"(p));
    lo = __uint_as_float(a); hi = __uint_as_float(b);
}

// ---------------------------------------------------------------------------
// Kernel B: symmetrized coefficients, wp folded in via re-association.
// One block per monomial m (220 blocks), 640 threads = (e,k).
//   Phase 1: UsT[b][o]  (symmetrized U, transposed, padded)
//   Phase 2: V[a][o] = sum_b proj[a][aoff+b] * UsT[b][o]   ((e,k)-independent)
//   Phase 3: S[ek][m][o] = sum_a w[e,a,k] * V[a][o]
// ---------------------------------------------------------------------------
__global__ void __launch_bounds__(NEK)
coeff_kernel(const float* __restrict__ w,
             const float* __restrict__ proj,
             const float* __restrict__ U1,
             const float* __restrict__ U2,
             const float* __restrict__ U3) {
    const int m = blockIdx.x;
    int mi = 9, mj = 9, ml = 9;
    {
        int c = 0;
        for (int i = 0; i < 10; i++)
            for (int j = i; j < 10; j++)
                for (int l = j; l < 10; l++) {
                    if (c == m) { mi = i; mj = j; ml = l; }
                    c++;
                }
    }
    const int deg  = (ml < 9) ? 3 : (mj < 9) ? 2 : (mi < 9) ? 1 : 0;
    const int aoff = (deg == 3) ? (NA1 + NA2) : (deg == 2) ? NA1 : 0;
    const int acnt = (deg == 3) ? NA3 : (deg == 2) ? NA2 : (deg == 1) ? NA1 : 0;

    __shared__ __align__(16) float UsT[NA3 * 12];   // [b][o], padded
    __shared__ __align__(16) float V[ATOT * 12];    // [a][o], padded

    const int t = threadIdx.x;
    if (t < NA3 * 12) UsT[t] = 0.f;
    __syncthreads();

    if (t < 9 * NA3) {
        int o = t / NA3, a = t % NA3;
        float s = 0.f;
        if (deg == 3) {
            int P[6][3] = {{mi,mj,ml},{mi,ml,mj},{mj,mi,ml},
                           {mj,ml,mi},{ml,mi,mj},{ml,mj,mi}};
#pragma unroll
            for (int p = 0; p < 6; p++) {
                bool dup = false;
#pragma unroll
                for (int q = 0; q < 6; q++)
                    if (q < p && P[q][0] == P[p][0] && P[q][1] == P[p][1] &&
                        P[q][2] == P[p][2]) dup = true;
                if (!dup)
                    s += U3[((((size_t)o * 9 + P[p][0]) * 9 + P[p][1]) * 9 + P[p][2]) * NA3 + a];
            }
        } else if (deg == 2 && a < NA2) {
            s = U2[(((size_t)o * 9 + mi) * 9 + mj) * NA2 + a];
            if (mi != mj)
                s += U2[(((size_t)o * 9 + mj) * 9 + mi) * NA2 + a];
        } else if (deg == 1 && a < NA1) {
            s = U1[((size_t)o * 9 + mi) * NA1 + a];
        }
        UsT[a * 12 + o] = s;
    }
    __syncthreads();

    // Phase 2: V[a][o], 29*9 = 261 entries (plus zero padding lanes)
    if (t < ATOT * 12) {
        int a = t / 12, o = t % 12;
        float s = 0.f;
        if (o < 9) {
            for (int b = 0; b < acnt; b++)
                s = fmaf(proj[a * ATOT + aoff + b], UsT[b * 12 + o], s);
        }
        V[a * 12 + o] = s;
    }
    __syncthreads();

    // Phase 3: per (e,k) thread
    const int e = t >> 6, k = t & 63;

    unsigned long long a01 = 0, a23 = 0, a45 = 0, a67 = 0;
    float a8 = 0.f;
#pragma unroll
    for (int a = 0; a < ATOT; a++) {
        float wa = w[((size_t)e * ATOT + a) * KCH + k];
        const float* row = V + a * 12;
        ulonglong2 cA = *(const ulonglong2*)row;
        ulonglong2 cB = *(const ulonglong2*)(row + 4);
        float c8 = row[8];
        unsigned long long wv = dup_f32(wa);
        ffma2(a01, cA.x, wv);
        ffma2(a23, cA.y, wv);
        ffma2(a45, cB.x, wv);
        ffma2(a67, cB.y, wv);
        a8 = fmaf(c8, wa, a8);
    }

    float c9[9];
    unpack2(a01, c9[0], c9[1]);
    unpack2(a23, c9[2], c9[3]);
    unpack2(a45, c9[4], c9[5]);
    unpack2(a67, c9[6], c9[7]);
    c9[8] = a8;

    float* dst = g_S + ((size_t)t * NM + m) * ROWF;
    ((float4*)dst)[0] = make_float4(c9[0], c9[1], c9[2], c9[3]);
    ((float4*)dst)[1] = make_float4(c9[4], c9[5], c9[6], c9[7]);
    dst[8] = c9[8];
}

// ---------------------------------------------------------------------------
// Eval inner body: accumulate monomials m in [MS, ME) into r[9].
// Fully unrolled; range guard folds at compile time.
// ---------------------------------------------------------------------------
template <int MS, int ME>
__device__ __forceinline__ void eval_range(const float* __restrict__ Cs,
                                           const float v[10], float r[9]) {
    unsigned long long a01 = 0, a23 = 0, a45 = 0, a67 = 0;
    float a8 = 0.f;
    int m = 0;
#pragma unroll
    for (int i = 0; i < 10; i++) {
#pragma unroll
        for (int j = i; j < 10; j++) {
            float pij = v[i] * v[j];
#pragma unroll
            for (int l = j; l < 10; l++) {
                if (m >= MS && m < ME) {
                    float tm = pij * v[l];
                    const float* row = Cs + m * ROWF;
                    ulonglong2 cA = *(const ulonglong2*)row;        // o0..3
                    ulonglong2 cB = *(const ulonglong2*)(row + 4);  // o4..7
                    float c8 = row[8];
                    unsigned long long tt = dup_f32(tm);
                    ffma2(a01, cA.x, tt);
                    ffma2(a23, cA.y, tt);
                    ffma2(a45, cB.x, tt);
                    ffma2(a67, cB.y, tt);
                    a8 = fmaf(c8, tm, a8);
                }
                m++;
            }
        }
    }
    unpack2(a01, r[0], r[1]);
    unpack2(a23, r[2], r[3]);
    unpack2(a45, r[4], r[5]);
    unpack2(a67, r[6], r[7]);
    r[8] = a8;
}

// ---------------------------------------------------------------------------
// Kernel C: evaluate. One block per (k, e), 512 threads.
//   atom = tid & 127, quarter = tid >> 7 sums 55 monomials each.
//   x is staged through smem with COALESCED global loads (the x layout
//   x[n][k][d] with lane=n is 1 line per lane if read directly — this was
//   the L1 bottleneck). Output staged the same way.
// ---------------------------------------------------------------------------
__global__ void __launch_bounds__(512)
eval_kernel(const float* __restrict__ x,
            const int* __restrict__ counts,
            float* __restrict__ out) {
    const int k = blockIdx.x;
    const int e = blockIdx.y;
    const int ek = e * KCH + k;

    __shared__ __align__(16) float Cs[NM * ROWF];
    __shared__ float Red[3 * 128 * RROW];
    __shared__ float Xs[128 * RROW];
    {
        const float4* src = (const float4*)(g_S + (size_t)ek * NM * ROWF);
        float4* dst = (float4*)Cs;
        for (int t = threadIdx.x; t < NM * ROWF / 4; t += blockDim.x)
            dst[t] = src[t];
    }

    int start = 0, cnt = 0;
#pragma unroll
    for (int t = 0; t < NSPEC; t++) {
        int c = counts[t];
        if (t < e) start += c;
        if (t == e) cnt = c;
    }

    // Coalesced cooperative x stage: Xs[atom][d] = x[(n*64+k)*9+d]
    for (int idx = threadIdx.x; idx < 128 * D; idx += blockDim.x) {
        int atom = idx / D, d = idx - atom * D;
        int a = atom < cnt ? atom : (cnt - 1);       // clamp (avoid OOB)
        int n = start + a;
        Xs[atom * RROW + d] = x[((size_t)n * KCH + k) * D + d];
    }
    __syncthreads();

    const int tid  = threadIdx.x;
    const int atom = tid & 127;
    const int q    = tid >> 7;

    float v[10];
#pragma unroll
    for (int t = 0; t < 9; t++) v[t] = Xs[atom * RROW + t];
    v[9] = 1.f;

    float r[9];
    if (q == 0)      eval_range<0,  Q1>(Cs, v, r);
    else if (q == 1) eval_range<Q1, Q2>(Cs, v, r);
    else if (q == 2) eval_range<Q2, Q3>(Cs, v, r);
    else             eval_range<Q3, NM>(Cs, v, r);

    if (q != 0) {
        float* rr = Red + ((q - 1) * 128 + atom) * RROW;
#pragma unroll
        for (int o = 0; o < 9; o++) rr[o] = r[o];
    }
    __syncthreads();

    // q0 reduces into Xs (x no longer needed), then coalesced store sweep
    if (q == 0) {
        const float* r1 = Red + (0 * 128 + atom) * RROW;
        const float* r2 = Red + (1 * 128 + atom) * RROW;
        const float* r3 = Red + (2 * 128 + atom) * RROW;
        float* rr = Xs + atom * RROW;
#pragma unroll
        for (int o = 0; o < 9; o++)
            rr[o] = (r[o] + r1[o]) + (r2[o] + r3[o]);
    }
    __syncthreads();

    for (int idx = threadIdx.x; idx < cnt * D; idx += blockDim.x) {
        int atom2 = idx / D, d = idx - atom2 * D;
        int n = start + atom2;
        out[((size_t)n * KCH + k) * D + d] = Xs[atom2 * RROW + d];
    }
}

// ---------------------------------------------------------------------------
extern "C" void kernel_launch(void* const* d_in, const int* in_sizes, int n_in,
                              void* d_out, int out_size) {
    const float* x      = (const float*)d_in[0];
    const int*   counts = (const int*)  d_in[1];
    const float* w      = (const float*)d_in[2];
    const float* proj   = (const float*)d_in[3];
    const float* U1     = (const float*)d_in[4];
    const float* U2     = (const float*)d_in[5];
    const float* U3     = (const float*)d_in[6];
    float* out = (float*)d_out;

    coeff_kernel<<<NM, NEK>>>(w, proj, U1, U2, U3);
    dim3 grid(KCH, NSPEC);
    eval_kernel<<<grid, 512>>>(x, counts, out);
}

// round 8
// speedup vs baseline: 1.2369x; 1.0121x over previous
#include <cuda_runtime.h>
#include <cstddef>

#define NSPEC 10
#define KCH   64
#define D     9
#define NA1   3
#define NA2   8
#define NA3   18
#define ATOT  29
#define NEK   (NSPEC * KCH)   // 640 (species, channel) combos
#define NM    220             // C(12,3): monomials i<=j<=l over 10 vars (v9 == 1)
#define ROWF  12              // padded floats per monomial row (9 outputs + 3 pad)
#define RROW  13              // reduction/x row stride (odd -> conflict-free banks)
#define Q1    55
#define Q2    110
#define Q3    165

// Scratch (device global — allocation-free per harness rules)
__device__ float g_S[(size_t)NEK * NM * ROWF];    // S[ek][m][o] symmetrized coeffs

// ---------------------------------------------------------------------------
// packed f32x2 helpers (sm_103a FFMA2 — PTX only)
// ---------------------------------------------------------------------------
__device__ __forceinline__ void ffma2(unsigned long long& d,
                                      unsigned long long a,
                                      unsigned long long b) {
    asm("fma.rn.f32x2 %0, %1, %2, %0;" : "+l"(d) : "l"(a), "l"(b));
}
__device__ __forceinline__ unsigned long long dup_f32(float t) {
    unsigned long long r;
    asm("mov.b64 %0, {%1, %1};" : "=l"(r) : "r"(__float_as_uint(t)));
    return r;
}
__device__ __forceinline__ void unpack2(unsigned long long p, float& lo, float& hi) {
    unsigned a, b;
    asm("mov.b64 {%0, %1}, %2;" : "=r"(a), "=r"(b) : "l"(p));
    lo = __uint_as_float(a); hi = __uint_as_float(b);
}

// ---------------------------------------------------------------------------
// Kernel B: symmetrized coefficients, wp folded in via re-association.
// One block per monomial m (220 blocks), 640 threads = (e,k).
//   Phase 1: UsT[b][o]  (symmetrized U, transposed, padded)
//   Phase 2: V[a][o] = sum_b proj[a][aoff+b] * UsT[b][o]   ((e,k)-independent)
//   Phase 3: S[ek][m][o] = sum_a w[e,a,k] * V[a][o]
// ---------------------------------------------------------------------------
__global__ void __launch_bounds__(NEK)
coeff_kernel(const float* __restrict__ w,
             const float* __restrict__ proj,
             const float* __restrict__ U1,
             const float* __restrict__ U2,
             const float* __restrict__ U3) {
    const int m = blockIdx.x;
    int mi = 9, mj = 9, ml = 9;
    {
        int c = 0;
        for (int i = 0; i < 10; i++)
            for (int j = i; j < 10; j++)
                for (int l = j; l < 10; l++) {
                    if (c == m) { mi = i; mj = j; ml = l; }
                    c++;
                }
    }
    const int deg  = (ml < 9) ? 3 : (mj < 9) ? 2 : (mi < 9) ? 1 : 0;
    const int aoff = (deg == 3) ? (NA1 + NA2) : (deg == 2) ? NA1 : 0;
    const int acnt = (deg == 3) ? NA3 : (deg == 2) ? NA2 : (deg == 1) ? NA1 : 0;

    __shared__ __align__(16) float UsT[NA3 * 12];   // [b][o], padded
    __shared__ __align__(16) float V[ATOT * 12];    // [a][o], padded

    const int t = threadIdx.x;
    if (t < NA3 * 12) UsT[t] = 0.f;
    __syncthreads();

    if (t < 9 * NA3) {
        int o = t / NA3, a = t % NA3;
        float s = 0.f;
        if (deg == 3) {
            int P[6][3] = {{mi,mj,ml},{mi,ml,mj},{mj,mi,ml},
                           {mj,ml,mi},{ml,mi,mj},{ml,mj,mi}};
#pragma unroll
            for (int p = 0; p < 6; p++) {
                bool dup = false;
#pragma unroll
                for (int q = 0; q < 6; q++)
                    if (q < p && P[q][0] == P[p][0] && P[q][1] == P[p][1] &&
                        P[q][2] == P[p][2]) dup = true;
                if (!dup)
                    s += U3[((((size_t)o * 9 + P[p][0]) * 9 + P[p][1]) * 9 + P[p][2]) * NA3 + a];
            }
        } else if (deg == 2 && a < NA2) {
            s = U2[(((size_t)o * 9 + mi) * 9 + mj) * NA2 + a];
            if (mi != mj)
                s += U2[(((size_t)o * 9 + mj) * 9 + mi) * NA2 + a];
        } else if (deg == 1 && a < NA1) {
            s = U1[((size_t)o * 9 + mi) * NA1 + a];
        }
        UsT[a * 12 + o] = s;
    }
    __syncthreads();

    // Phase 2: V[a][o], 29*9 = 261 entries (plus zero padding lanes)
    if (t < ATOT * 12) {
        int a = t / 12, o = t % 12;
        float s = 0.f;
        if (o < 9) {
            for (int b = 0; b < acnt; b++)
                s = fmaf(proj[a * ATOT + aoff + b], UsT[b * 12 + o], s);
        }
        V[a * 12 + o] = s;
    }
    __syncthreads();

    // Phase 3: per (e,k) thread
    const int e = t >> 6, k = t & 63;

    unsigned long long a01 = 0, a23 = 0, a45 = 0, a67 = 0;
    float a8 = 0.f;
#pragma unroll
    for (int a = 0; a < ATOT; a++) {
        float wa = w[((size_t)e * ATOT + a) * KCH + k];
        const float* row = V + a * 12;
        ulonglong2 cA = *(const ulonglong2*)row;
        ulonglong2 cB = *(const ulonglong2*)(row + 4);
        float c8 = row[8];
        unsigned long long wv = dup_f32(wa);
        ffma2(a01, cA.x, wv);
        ffma2(a23, cA.y, wv);
        ffma2(a45, cB.x, wv);
        ffma2(a67, cB.y, wv);
        a8 = fmaf(c8, wa, a8);
    }

    float c9[9];
    unpack2(a01, c9[0], c9[1]);
    unpack2(a23, c9[2], c9[3]);
    unpack2(a45, c9[4], c9[5]);
    unpack2(a67, c9[6], c9[7]);
    c9[8] = a8;

    float* dst = g_S + ((size_t)t * NM + m) * ROWF;
    ((float4*)dst)[0] = make_float4(c9[0], c9[1], c9[2], c9[3]);
    ((float4*)dst)[1] = make_float4(c9[4], c9[5], c9[6], c9[7]);
    ((float4*)dst)[2] = make_float4(c9[8], 0.f, 0.f, 0.f);   // zeroed pad
}

// ---------------------------------------------------------------------------
// Eval inner body: accumulate monomials m in [MS, ME) into r[9].
// Fully unrolled; range guard folds at compile time.
// ---------------------------------------------------------------------------
template <int MS, int ME>
__device__ __forceinline__ void eval_range(const float* __restrict__ Cs,
                                           const float v[10], float r[9]) {
    unsigned long long a01 = 0, a23 = 0, a45 = 0, a67 = 0;
    float a8 = 0.f;
    int m = 0;
#pragma unroll
    for (int i = 0; i < 10; i++) {
#pragma unroll
        for (int j = i; j < 10; j++) {
            float pij = v[i] * v[j];
#pragma unroll
            for (int l = j; l < 10; l++) {
                if (m >= MS && m < ME) {
                    float tm = pij * v[l];
                    const float* row = Cs + m * ROWF;
                    ulonglong2 cA = *(const ulonglong2*)row;        // o0..3
                    ulonglong2 cB = *(const ulonglong2*)(row + 4);  // o4..7
                    float c8 = row[8];
                    unsigned long long tt = dup_f32(tm);
                    ffma2(a01, cA.x, tt);
                    ffma2(a23, cA.y, tt);
                    ffma2(a45, cB.x, tt);
                    ffma2(a67, cB.y, tt);
                    a8 = fmaf(c8, tm, a8);
                }
                m++;
            }
        }
    }
    unpack2(a01, r[0], r[1]);
    unpack2(a23, r[2], r[3]);
    unpack2(a45, r[4], r[5]);
    unpack2(a67, r[6], r[7]);
    r[8] = a8;
}

// ---------------------------------------------------------------------------
// Kernel C: evaluate. One block per (k, e), 512 threads, min 3 blocks/SM
// (register-occupancy was the binding constraint at 43 regs -> 2 blocks/SM).
//   atom = tid & 127, quarter = tid >> 7 sums 55 monomials each.
//   x and out staged through smem with coalesced global access.
// ---------------------------------------------------------------------------
__global__ void __launch_bounds__(512, 3)
eval_kernel(const float* __restrict__ x,
            const int* __restrict__ counts,
            float* __restrict__ out) {
    const int k = blockIdx.x;
    const int e = blockIdx.y;
    const int ek = e * KCH + k;

    __shared__ __align__(16) float Cs[NM * ROWF];
    __shared__ float Red[3 * 128 * RROW];
    __shared__ float Xs[128 * RROW];
    {
        const float4* src = (const float4*)(g_S + (size_t)ek * NM * ROWF);
        float4* dst = (float4*)Cs;
        for (int t = threadIdx.x; t < NM * ROWF / 4; t += blockDim.x)
            dst[t] = src[t];
    }

    int start = 0, cnt = 0;
#pragma unroll
    for (int t = 0; t < NSPEC; t++) {
        int c = counts[t];
        if (t < e) start += c;
        if (t == e) cnt = c;
    }

    // Coalesced cooperative x stage: Xs[atom][d] = x[(n*64+k)*9+d]
    for (int idx = threadIdx.x; idx < 128 * D; idx += blockDim.x) {
        int atom = idx / D, d = idx - atom * D;
        int a = atom < cnt ? atom : (cnt - 1);       // clamp (avoid OOB)
        int n = start + a;
        Xs[atom * RROW + d] = x[((size_t)n * KCH + k) * D + d];
    }
    __syncthreads();

    const int tid  = threadIdx.x;
    const int atom = tid & 127;
    const int q    = tid >> 7;

    float v[10];
#pragma unroll
    for (int t = 0; t < 9; t++) v[t] = Xs[atom * RROW + t];
    v[9] = 1.f;

    float r[9];
    if (q == 0)      eval_range<0,  Q1>(Cs, v, r);
    else if (q == 1) eval_range<Q1, Q2>(Cs, v, r);
    else if (q == 2) eval_range<Q2, Q3>(Cs, v, r);
    else             eval_range<Q3, NM>(Cs, v, r);

    if (q != 0) {
        float* rr = Red + ((q - 1) * 128 + atom) * RROW;
#pragma unroll
        for (int o = 0; o < 9; o++) rr[o] = r[o];
    }
    __syncthreads();

    // q0 reduces into Xs (x no longer needed), then coalesced store sweep
    if (q == 0) {
        const float* r1 = Red + (0 * 128 + atom) * RROW;
        const float* r2 = Red + (1 * 128 + atom) * RROW;
        const float* r3 = Red + (2 * 128 + atom) * RROW;
        float* rr = Xs + atom * RROW;
#pragma unroll
        for (int o = 0; o < 9; o++)
            rr[o] = (r[o] + r1[o]) + (r2[o] + r3[o]);
    }
    __syncthreads();

    for (int idx = threadIdx.x; idx < cnt * D; idx += blockDim.x) {
        int atom2 = idx / D, d = idx - atom2 * D;
        int n = start + atom2;
        out[((size_t)n * KCH + k) * D + d] = Xs[atom2 * RROW + d];
    }
}

// ---------------------------------------------------------------------------
extern "C" void kernel_launch(void* const* d_in, const int* in_sizes, int n_in,
                              void* d_out, int out_size) {
    const float* x      = (const float*)d_in[0];
    const int*   counts = (const int*)  d_in[1];
    const float* w      = (const float*)d_in[2];
    const float* proj   = (const float*)d_in[3];
    const float* U1     = (const float*)d_in[4];
    const float* U2     = (const float*)d_in[5];
    const float* U3     = (const float*)d_in[6];
    float* out = (float*)d_out;

    coeff_kernel<<<NM, NEK>>>(w, proj, U1, U2, U3);
    dim3 grid(KCH, NSPEC);
    eval_kernel<<<grid, 512>>>(x, counts, out);
}

// round 10
// speedup vs baseline: 1.8455x; 1.4921x over previous
#include <cuda_runtime.h>
#include <cstddef>

#define NSPEC 10
#define KCH   64
#define D     9
#define NA1   3
#define NA2   8
#define NA3   18
#define ATOT  29
#define NEK   (NSPEC * KCH)   // 640 (species, channel) combos
#define NM    220             // C(12,3): monomials i<=j<=l over 10 vars (v9 == 1)
#define ROWF  12              // padded floats per monomial row (9 outputs + 3 pad)
#define RROW  13              // reduction/x row stride (odd -> conflict-free banks)
#define Q1    55
#define Q2    110
#define Q3    165

// Scratch (device global — allocation-free per harness rules)
__device__ float g_S[(size_t)NEK * NM * ROWF];    // S[ek][m][o] symmetrized coeffs

// ---------------------------------------------------------------------------
// packed f32x2 helpers (sm_103a FFMA2 — PTX only)
// ---------------------------------------------------------------------------
__device__ __forceinline__ void ffma2(unsigned long long& d,
                                      unsigned long long a,
                                      unsigned long long b) {
    asm("fma.rn.f32x2 %0, %1, %2, %0;" : "+l"(d) : "l"(a), "l"(b));
}
__device__ __forceinline__ unsigned long long dup_f32(float t) {
    unsigned long long r;
    asm("mov.b64 %0, {%1, %1};" : "=l"(r) : "r"(__float_as_uint(t)));
    return r;
}
__device__ __forceinline__ void unpack2(unsigned long long p, float& lo, float& hi) {
    unsigned a, b;
    asm("mov.b64 {%0, %1}, %2;" : "=r"(a), "=r"(b) : "l"(p));
    lo = __uint_as_float(a); hi = __uint_as_float(b);
}

// ---------------------------------------------------------------------------
// Kernel B: symmetrized coefficients, wp folded in via re-association.
// One block per monomial m (220 blocks), 640 threads = (e,k).
//   Phase 1: UsT[b][o]  (symmetrized U, transposed, padded) — branch-free:
//            sum over ALL 6 ordered perms, scaled by (#distinct)/6.
//   Phase 2: V[a][o] = sum_b proj[a][aoff+b] * UsT[b][o]  (unrolled per degree)
//   Phase 3: S[ek][m][o] = sum_a w[e,a,k] * V[a][o]  (w prefetched at entry)
// ---------------------------------------------------------------------------
__global__ void __launch_bounds__(NEK)
coeff_kernel(const float* __restrict__ w,
             const float* __restrict__ proj,
             const float* __restrict__ U1,
             const float* __restrict__ U2,
             const float* __restrict__ U3) {
    const int m = blockIdx.x;
    const int t = threadIdx.x;

    // --- prefetch w for phase 3 (hides LDG latency under phases 1-2) ---
    const int e = t >> 6, k = t & 63;
    float wr[ATOT];
#pragma unroll
    for (int a = 0; a < ATOT; a++)
        wr[a] = w[((size_t)e * ATOT + a) * KCH + k];

    // --- closed-form decode m -> (mi <= mj <= ml) over 10 vars ---
    int rem = m, mi = 0, mj, ml;
#pragma unroll
    for (int i = 0; i < 10; i++) {
        int tt = 10 - i, c = tt * (tt + 1) / 2;
        if (rem >= c) rem -= c; else { mi = i; break; }
    }
    mj = mi;
#pragma unroll
    for (int j = 0; j < 10; j++) {
        if (j < mi) continue;
        int c = 10 - j;
        if (rem >= c) rem -= c; else { mj = j; break; }
    }
    ml = mj + rem;

    const int deg  = (ml < 9) ? 3 : (mj < 9) ? 2 : (mi < 9) ? 1 : 0;
    const int aoff = (deg == 3) ? (NA1 + NA2) : (deg == 2) ? NA1 : 0;

    __shared__ __align__(16) float UsT[NA3 * 12];   // [b][o], padded
    __shared__ __align__(16) float V[ATOT * 12];    // [a][o], padded

    if (t < NA3 * 12) UsT[t] = 0.f;
    __syncthreads();

    if (t < 9 * NA3) {
        int o = t / NA3, a = t % NA3;
        float s = 0.f;
        if (deg == 3) {
            // branch-free: all 6 ordered perms, scale = #distinct / 6
            const size_t ob = (size_t)o * 9;
            float s6 =
                U3[(((ob + mi) * 9 + mj) * 9 + ml) * NA3 + a] +
                U3[(((ob + mi) * 9 + ml) * 9 + mj) * NA3 + a] +
                U3[(((ob + mj) * 9 + mi) * 9 + ml) * NA3 + a] +
                U3[(((ob + mj) * 9 + ml) * 9 + mi) * NA3 + a] +
                U3[(((ob + ml) * 9 + mi) * 9 + mj) * NA3 + a] +
                U3[(((ob + ml) * 9 + mj) * 9 + mi) * NA3 + a];
            float scale = (mi == ml) ? (1.f / 6.f)
                         : ((mi == mj || mj == ml) ? 0.5f : 1.f);
            s = s6 * scale;
        } else if (deg == 2 && a < NA2) {
            float s2 = U2[(((size_t)o * 9 + mi) * 9 + mj) * NA2 + a] +
                       U2[(((size_t)o * 9 + mj) * 9 + mi) * NA2 + a];
            s = (mi == mj) ? 0.5f * s2 : s2;
        } else if (deg == 1 && a < NA1) {
            s = U1[((size_t)o * 9 + mi) * NA1 + a];
        }
        UsT[a * 12 + o] = s;                       // (round-9 typo fixed here)
    }
    __syncthreads();

    // Phase 2: V[a][o]  (compile-time unrolled per degree)
    if (t < ATOT * 12) {
        int a = t / 12, o = t % 12;
        float s = 0.f;
        if (o < 9) {
            if (deg == 3) {
#pragma unroll
                for (int b = 0; b < NA3; b++)
                    s = fmaf(proj[a * ATOT + aoff + b], UsT[b * 12 + o], s);
            } else if (deg == 2) {
#pragma unroll
                for (int b = 0; b < NA2; b++)
                    s = fmaf(proj[a * ATOT + aoff + b], UsT[b * 12 + o], s);
            } else if (deg == 1) {
#pragma unroll
                for (int b = 0; b < NA1; b++)
                    s = fmaf(proj[a * ATOT + aoff + b], UsT[b * 12 + o], s);
            }
        }
        V[a * 12 + o] = s;
    }
    __syncthreads();

    // Phase 3: per (e,k) thread, w already in registers
    unsigned long long a01 = 0, a23 = 0, a45 = 0, a67 = 0;
    float a8 = 0.f;
#pragma unroll
    for (int a = 0; a < ATOT; a++) {
        const float* row = V + a * 12;
        ulonglong2 cA = *(const ulonglong2*)row;
        ulonglong2 cB = *(const ulonglong2*)(row + 4);
        float c8 = row[8];
        unsigned long long wv = dup_f32(wr[a]);
        ffma2(a01, cA.x, wv);
        ffma2(a23, cA.y, wv);
        ffma2(a45, cB.x, wv);
        ffma2(a67, cB.y, wv);
        a8 = fmaf(c8, wr[a], a8);
    }

    float c9[9];
    unpack2(a01, c9[0], c9[1]);
    unpack2(a23, c9[2], c9[3]);
    unpack2(a45, c9[4], c9[5]);
    unpack2(a67, c9[6], c9[7]);
    c9[8] = a8;

    float* dst = g_S + ((size_t)t * NM + m) * ROWF;
    ((float4*)dst)[0] = make_float4(c9[0], c9[1], c9[2], c9[3]);
    ((float4*)dst)[1] = make_float4(c9[4], c9[5], c9[6], c9[7]);
    ((float4*)dst)[2] = make_float4(c9[8], 0.f, 0.f, 0.f);   // zeroed pad
}

// ---------------------------------------------------------------------------
// Eval inner body: accumulate monomials m in [MS, ME) into r[9].
// Fully unrolled; range guard folds at compile time.
// ---------------------------------------------------------------------------
template <int MS, int ME>
__device__ __forceinline__ void eval_range(const float* __restrict__ Cs,
                                           const float v[10], float r[9]) {
    unsigned long long a01 = 0, a23 = 0, a45 = 0, a67 = 0;
    float a8 = 0.f;
    int m = 0;
#pragma unroll
    for (int i = 0; i < 10; i++) {
#pragma unroll
        for (int j = i; j < 10; j++) {
            float pij = v[i] * v[j];
#pragma unroll
            for (int l = j; l < 10; l++) {
                if (m >= MS && m < ME) {
                    float tm = pij * v[l];
                    const float* row = Cs + m * ROWF;
                    ulonglong2 cA = *(const ulonglong2*)row;        // o0..3
                    ulonglong2 cB = *(const ulonglong2*)(row + 4);  // o4..7
                    float c8 = row[8];
                    unsigned long long tt = dup_f32(tm);
                    ffma2(a01, cA.x, tt);
                    ffma2(a23, cA.y, tt);
                    ffma2(a45, cB.x, tt);
                    ffma2(a67, cB.y, tt);
                    a8 = fmaf(c8, tm, a8);
                }
                m++;
            }
        }
    }
    unpack2(a01, r[0], r[1]);
    unpack2(a23, r[2], r[3]);
    unpack2(a45, r[4], r[5]);
    unpack2(a67, r[6], r[7]);
    r[8] = a8;
}

// ---------------------------------------------------------------------------
// Kernel C: evaluate. One block per (k, e), 512 threads, min 3 blocks/SM.
//   atom = tid & 127, quarter = tid >> 7 sums 55 monomials each.
//   x and out staged through smem with coalesced global access.
// ---------------------------------------------------------------------------
__global__ void __launch_bounds__(512, 3)
eval_kernel(const float* __restrict__ x,
            const int* __restrict__ counts,
            float* __restrict__ out) {
    const int k = blockIdx.x;
    const int e = blockIdx.y;
    const int ek = e * KCH + k;

    __shared__ __align__(16) float Cs[NM * ROWF];
    __shared__ float Red[3 * 128 * RROW];
    __shared__ float Xs[128 * RROW];
    {
        const float4* src = (const float4*)(g_S + (size_t)ek * NM * ROWF);
        float4* dst = (float4*)Cs;
        for (int t = threadIdx.x; t < NM * ROWF / 4; t += blockDim.x)
            dst[t] = src[t];
    }

    int start = 0, cnt = 0;
#pragma unroll
    for (int t = 0; t < NSPEC; t++) {
        int c = counts[t];
        if (t < e) start += c;
        if (t == e) cnt = c;
    }

    // Coalesced cooperative x stage: Xs[atom][d] = x[(n*64+k)*9+d]
    for (int idx = threadIdx.x; idx < 128 * D; idx += blockDim.x) {
        int atom = idx / D, d = idx - atom * D;
        int a = atom < cnt ? atom : (cnt - 1);       // clamp (avoid OOB)
        int n = start + a;
        Xs[atom * RROW + d] = x[((size_t)n * KCH + k) * D + d];
    }
    __syncthreads();

    const int tid  = threadIdx.x;
    const int atom = tid & 127;
    const int q    = tid >> 7;

    float v[10];
#pragma unroll
    for (int t = 0; t < 9; t++) v[t] = Xs[atom * RROW + t];
    v[9] = 1.f;

    float r[9];
    if (q == 0)      eval_range<0,  Q1>(Cs, v, r);
    else if (q == 1) eval_range<Q1, Q2>(Cs, v, r);
    else if (q == 2) eval_range<Q2, Q3>(Cs, v, r);
    else             eval_range<Q3, NM>(Cs, v, r);

    if (q != 0) {
        float* rr = Red + ((q - 1) * 128 + atom) * RROW;
#pragma unroll
        for (int o = 0; o < 9; o++) rr[o] = r[o];
    }
    __syncthreads();

    // q0 reduces into Xs (x no longer needed), then coalesced store sweep
    if (q == 0) {
        const float* r1 = Red + (0 * 128 + atom) * RROW;
        const float* r2 = Red + (1 * 128 + atom) * RROW;
        const float* r3 = Red + (2 * 128 + atom) * RROW;
        float* rr = Xs + atom * RROW;
#pragma unroll
        for (int o = 0; o < 9; o++)
            rr[o] = (r[o] + r1[o]) + (r2[o] + r3[o]);
    }
    __syncthreads();

    for (int idx = threadIdx.x; idx < cnt * D; idx += blockDim.x) {
        int atom2 = idx / D, d = idx - atom2 * D;
        int n = start + atom2;
        out[((size_t)n * KCH + k) * D + d] = Xs[atom2 * RROW + d];
    }
}

// ---------------------------------------------------------------------------
extern "C" void kernel_launch(void* const* d_in, const int* in_sizes, int n_in,
                              void* d_out, int out_size) {
    const float* x      = (const float*)d_in[0];
    const int*   counts = (const int*)  d_in[1];
    const float* w      = (const float*)d_in[2];
    const float* proj   = (const float*)d_in[3];
    const float* U1     = (const float*)d_in[4];
    const float* U2     = (const float*)d_in[5];
    const float* U3     = (const float*)d_in[6];
    float* out = (float*)d_out;

    coeff_kernel<<<NM, NEK>>>(w, proj, U1, U2, U3);
    dim3 grid(KCH, NSPEC);
    eval_kernel<<<grid, 512>>>(x, counts, out);
}